// round 8
// baseline (speedup 1.0000x reference)
#include <cuda_runtime.h>
#include <math.h>
#include <stdint.h>

// Problem constants
#define NB 32
#define ND 64
#define NT 4096
#define NK 512
#define NTOK (NB * NT)          // 131072 tokens
#define TM 128                  // tokens per tile
#define NTILES (NTOK / TM)      // 1024 tiles
#define NCTA 148
#define ESTR 68                 // smem row stride (floats)

// Output layout (float32, reference tuple flattened in order)
#define Q_OFF     ((size_t)1)
#define PERP_OFF  ((size_t)1 + (size_t)NB * ND * NT)
#define IDX_OFF   (PERP_OFF + 1)

// Margin threshold: single-tf32 worst-case distance error ~0.1; 2 dists + norm slop < 0.35
#define THETA 0.35f
#define FLAG_CAP 32768

__device__ float g_loss;
__device__ unsigned int g_counts[NK];
__device__ unsigned int g_flagn;
__device__ int g_flags[FLAG_CAP];

__device__ __forceinline__ uint32_t tf32b(float v) {
    uint32_t u;
    asm("cvt.rna.tf32.f32 %0, %1;" : "=r"(u) : "f"(v));
    return u;
}

// m16n8k8 tf32 mma: D += A(16x8,row) * B(8x8,col)
__device__ __forceinline__ void mma_tf32(float* d, const uint32_t* a, const uint32_t* b) {
    asm volatile(
        "mma.sync.aligned.m16n8k8.row.col.f32.tf32.tf32.f32 "
        "{%0,%1,%2,%3}, {%4,%5,%6,%7}, {%8,%9}, {%0,%1,%2,%3};"
        : "+f"(d[0]), "+f"(d[1]), "+f"(d[2]), "+f"(d[3])
        : "r"(a[0]), "r"(a[1]), "r"(a[2]), "r"(a[3]), "r"(b[0]), "r"(b[1]));
}

// ================= K0: init =================
__global__ void vq_init() {
    int i = threadIdx.x;
    if (i == 0) { g_loss = 0.f; g_flagn = 0u; }
    if (i < NK) g_counts[i] = 0u;
}

// ================= K1: persistent tf32 GEMM + argmin + q/loss/hist + flags ==========
__global__ __launch_bounds__(512, 1) void vq_gemm(
    const float* __restrict__ in, const float* __restrict__ emb,
    float* __restrict__ out)
{
    extern __shared__ float smem[];
    float* sB   = smem;                      // NK x ESTR (ORIGINAL f32)   139264 B
    float* sA   = sB + NK * ESTR;            // TM x ESTR                   34816 B
    float* sEn  = sA + TM * ESTR;            // NK
    float* sXnP = sEn + NK;                  // 512 partials
    float* sXn  = sXnP + 512;                // TM
    float* bF   = sXn + TM;                  // TM (half1 best)
    float* sF   = bF + TM;                   // TM (half1 second)
    int*   iF   = (int*)(sF + TM);           // TM (half1 idx)
    int*   sIdx = iF + TM;                   // TM (final provisional idx)
    unsigned int* sCount = (unsigned int*)(sIdx + TM);  // NK
    __shared__ float sLoss;

    const int tid = threadIdx.x;
    const int wid = tid >> 5;
    const int lane = tid & 31;
    const int grp = lane >> 2;               // 0..7
    const int qid = lane & 3;                // 0..3
    const int h   = wid >> 3;                // n-half: 0 -> [0,256), 1 -> [256,512)
    const int m0  = (wid & 7) * 16;          // m-block rows

    if (tid == 0) sLoss = 0.f;
    if (tid < NK) sCount[tid] = 0u;

    // ---- Stage B once (original f32, padded stride) ----
    {
        const float4* e4 = (const float4*)emb;
        for (int i = tid; i < NK * ND / 4; i += 512) {
            int code = i >> 4, d4 = i & 15;
            float4 v = e4[i];
            *(float4*)(sB + code * ESTR + 4 * d4) = v;
        }
    }
    // ---- sEn once (sloppy f32 is fine: THETA covers) ----
    if (tid < NK) {
        const float* e = emb + tid * ND;
        float s = 0.f;
        #pragma unroll
        for (int d = 0; d < ND; d++) s = __fmaf_rn(e[d], e[d], s);
        sEn[tid] = s;
    }
    __syncthreads();

    float llocal = 0.f;

    for (int tile = blockIdx.x; tile < NTILES; tile += gridDim.x) {
        const int token0 = tile * TM;
        const int b = token0 >> 12;
        const int t0 = token0 & (NT - 1);

        // ---- Stage A: thread (tok = tid&127, dq = tid>>7) loads 16 d's; coalesced ----
        {
            const int tok = tid & 127, dq = tid >> 7;
            const float* xp = in + (size_t)b * ND * NT + (t0 + tok);
            float p = 0.f;
            float* ar = sA + tok * ESTR + dq * 16;
            #pragma unroll
            for (int i = 0; i < 16; i++) {
                float x = xp[(size_t)(dq * 16 + i) * NT];
                ar[i] = x;
                p = __fmaf_rn(x, x, p);
            }
            sXnP[tok + 128 * dq] = p;
        }
        __syncthreads();
        if (tid < TM)
            sXn[tid] = ((sXnP[tid] + sXnP[tid + 128]) +
                        (sXnP[tid + 256] + sXnP[tid + 384]));
        __syncthreads();

        // ---- A fragments (tf32) ----
        uint32_t ah[8][4];
        #pragma unroll
        for (int kk = 0; kk < 8; kk++) {
            const float* r0 = sA + (m0 + grp) * ESTR + kk * 8;
            const float* r8 = sA + (m0 + grp + 8) * ESTR + kk * 8;
            ah[kk][0] = tf32b(r0[qid]);
            ah[kk][1] = tf32b(r8[qid]);
            ah[kk][2] = tf32b(r0[qid + 4]);
            ah[kk][3] = tf32b(r8[qid + 4]);
        }
        const float xnA = sXn[m0 + grp];
        const float xnB = sXn[m0 + grp + 8];

        float bA = 3.4e38f, sA2 = 3.4e38f; int iA = 0;
        float bB = 3.4e38f, sB2 = 3.4e38f; int iB = 0;

        // ---- n-loop: this warp's half, 32 tiles of 8 codes ----
        #pragma unroll 1
        for (int nt = 0; nt < 32; nt++) {
            const int n0 = h * 256 + nt * 8;
            float acc[4] = {0.f, 0.f, 0.f, 0.f};
            const float* bp = sB + (n0 + grp) * ESTR;
            #pragma unroll
            for (int kk = 0; kk < 8; kk++) {
                uint32_t bb[2] = { tf32b(bp[kk * 8 + qid]), tf32b(bp[kk * 8 + qid + 4]) };
                mma_tf32(acc, ah[kk], bb);
            }
            const int c0 = n0 + 2 * qid;
            const float en0 = sEn[c0], en1 = sEn[c0 + 1];
            float d0 = (xnA + en0) - 2.f * acc[0];
            float d1 = (xnA + en1) - 2.f * acc[1];
            float d2 = (xnB + en0) - 2.f * acc[2];
            float d3 = (xnB + en1) - 2.f * acc[3];
            if (d0 < bA) { sA2 = bA; bA = d0; iA = c0; } else if (d0 < sA2) sA2 = d0;
            if (d1 < bA) { sA2 = bA; bA = d1; iA = c0 + 1; } else if (d1 < sA2) sA2 = d1;
            if (d2 < bB) { sB2 = bB; bB = d2; iB = c0; } else if (d2 < sB2) sB2 = d2;
            if (d3 < bB) { sB2 = bB; bB = d3; iB = c0 + 1; } else if (d3 < sB2) sB2 = d3;
        }

        // ---- merge across the 4 lanes of each row-group (tie -> lower index) ----
        #pragma unroll
        for (int m = 1; m <= 2; m <<= 1) {
            float ob = __shfl_xor_sync(0xffffffffu, bA, m);
            float os = __shfl_xor_sync(0xffffffffu, sA2, m);
            int   oi = __shfl_xor_sync(0xffffffffu, iA, m);
            if (ob < bA || (ob == bA && oi < iA)) { sA2 = fminf(bA, os); bA = ob; iA = oi; }
            else { sA2 = fminf(sA2, ob); }
            ob = __shfl_xor_sync(0xffffffffu, bB, m);
            os = __shfl_xor_sync(0xffffffffu, sB2, m);
            oi = __shfl_xor_sync(0xffffffffu, iB, m);
            if (ob < bB || (ob == bB && oi < iB)) { sB2 = fminf(bB, os); bB = ob; iB = oi; }
            else { sB2 = fminf(sB2, ob); }
        }

        // ---- half1 publishes, half0 merges (half0 idx < half1 idx always: tie -> half0) ----
        if (h == 1 && qid == 0) {
            int lA = m0 + grp, lB = lA + 8;
            bF[lA] = bA; sF[lA] = sA2; iF[lA] = iA;
            bF[lB] = bB; sF[lB] = sB2; iF[lB] = iB;
        }
        __syncthreads();
        if (h == 0 && qid == 0) {
            #pragma unroll
            for (int half = 0; half < 2; half++) {
                int l = m0 + grp + 8 * half;
                float mb = half ? bB : bA;
                float ms = half ? sB2 : sA2;
                int   mi = half ? iB : iA;
                float ob = bF[l], os = sF[l]; int oi = iF[l];
                float fb, fs; int fi;
                if (ob < mb) { fb = ob; fi = oi; fs = fminf(mb, os); }
                else         { fb = mb; fi = mi; fs = fminf(ms, ob); }
                sIdx[l] = fi;
                const int gtok = token0 + l;
                out[IDX_OFF + (size_t)gtok] = (float)fi;
                atomicAdd(&sCount[fi], 1u);
                if (!(fs - fb > THETA)) {       // tiny margin (or NaN) -> exact path
                    unsigned p = atomicAdd(&g_flagn, 1u);
                    if (p < FLAG_CAP) g_flags[p] = gtok;
                }
            }
        }
        __syncthreads();

        // ---- cooperative q-write + loss: all from smem; coalesced stores ----
        {
            const int tok = tid & 127, dq = tid >> 7;
            const int bidx = sIdx[tok];
            const float* er = sB + bidx * ESTR + dq * 16;
            const float* xr = sA + tok * ESTR + dq * 16;
            float* qp = out + Q_OFF + (size_t)b * ND * NT + (t0 + tok);
            #pragma unroll
            for (int i = 0; i < 16; i++) {
                float e = er[i];
                qp[(size_t)(dq * 16 + i) * NT] = e;
                float df = e - xr[i];
                llocal = __fmaf_rn(df, df, llocal);
            }
        }
        __syncthreads();   // protect sA/sIdx before next tile
    }

    // ---- flush loss + counts ----
    #pragma unroll
    for (int off = 16; off; off >>= 1)
        llocal += __shfl_down_sync(0xffffffffu, llocal, off);
    if (lane == 0) atomicAdd(&sLoss, llocal);
    __syncthreads();
    if (tid == 0) atomicAdd(&g_loss, sLoss);
    if (tid < NK) {
        unsigned c = sCount[tid];
        if (c) atomicAdd(&g_counts[tid], c);
    }
}

// ================= K2: exact frozen recompute for flagged tokens (4 slots/CTA) =======
__global__ __launch_bounds__(512, 1) void vq_cleanup(
    const float* __restrict__ in, const float* __restrict__ emb,
    float* __restrict__ out)
{
    __shared__ float sen[NK];
    __shared__ float sx[4][ND];
    __shared__ float sxn[4];
    __shared__ unsigned long long skey[4];
    __shared__ int schg[4];    // new idx if changed else -1
    __shared__ int sold[4];

    const int tid = threadIdx.x;
    const int wid = tid >> 5;
    const int lane = tid & 31;
    const int slot = tid >> 7;     // 0..3
    const int st = tid & 127;

    // FROZEN en (warp-tree, matches reference rounding)
    for (int k = wid; k < NK; k += 16) {
        const float* e = emb + k * ND;
        float a = __fmul_rn(e[lane], e[lane]);
        float c = __fmul_rn(e[lane + 32], e[lane + 32]);
        float acc = __fadd_rn(a, c);
        #pragma unroll
        for (int off = 16; off; off >>= 1)
            acc = __fadd_rn(acc, __shfl_down_sync(0xffffffffu, acc, off));
        if (lane == 0) sen[k] = acc;
    }
    __syncthreads();

    unsigned count = g_flagn;
    if (count > FLAG_CAP) count = FLAG_CAP;
    const unsigned gslots = gridDim.x * 4;
    const unsigned iters = (count + gslots - 1) / gslots;

    for (unsigned it = 0; it < iters; it++) {
        const unsigned fi = it * gslots + blockIdx.x * 4 + slot;
        const bool act = fi < count;
        int token = 0, b = 0, t = 0;
        if (act) {
            token = g_flags[fi];
            b = token >> 12; t = token & (NT - 1);
            if (st < ND) sx[slot][st] = in[(size_t)b * ND * NT + (size_t)st * NT + t];
            if (st == 0) skey[slot] = 0xFFFFFFFFFFFFFFFFull;
        }
        __syncthreads();
        if (act && st == 0) {
            float xn = 0.f;   // FROZEN: sequential ascending, no fma contraction
            for (int d = 0; d < ND; d++)
                xn = __fadd_rn(xn, __fmul_rn(sx[slot][d], sx[slot][d]));
            sxn[slot] = xn;
        }
        __syncthreads();
        if (act) {
            // thread handles 4 codes: st, st+128, st+256, st+384 (frozen sequential fma dot)
            float a0 = 0.f, a1 = 0.f, a2 = 0.f, a3 = 0.f;
            const float* e0 = emb + (st +   0) * ND;
            const float* e1 = emb + (st + 128) * ND;
            const float* e2 = emb + (st + 256) * ND;
            const float* e3 = emb + (st + 384) * ND;
            for (int d = 0; d < ND; d++) {
                float xv = sx[slot][d];
                a0 = __fmaf_rn(xv, e0[d], a0);
                a1 = __fmaf_rn(xv, e1[d], a1);
                a2 = __fmaf_rn(xv, e2[d], a2);
                a3 = __fmaf_rn(xv, e3[d], a3);
            }
            float xn = sxn[slot];
            #pragma unroll
            for (int j = 0; j < 4; j++) {
                float dot = (j == 0) ? a0 : (j == 1) ? a1 : (j == 2) ? a2 : a3;
                int k = st + 128 * j;
                float dist = __fadd_rn(__fadd_rn(xn, sen[k]), __fmul_rn(-2.f, dot));
                uint32_t u = __float_as_uint(dist);
                u = (u & 0x80000000u) ? ~u : (u | 0x80000000u);   // order-preserving
                unsigned long long key = ((unsigned long long)u << 32) | (unsigned)k;
                atomicMin(&skey[slot], key);   // min dist, tie -> min index
            }
        }
        __syncthreads();
        if (act && st == 0) {
            int nidx = (int)(unsigned)(skey[slot] & 0xFFFFFFFFu);
            int oidx = (int)out[IDX_OFF + (size_t)token];
            sold[slot] = oidx;
            schg[slot] = (nidx != oidx) ? nidx : -1;
            if (nidx != oidx) out[IDX_OFF + (size_t)token] = (float)nidx;
        }
        __syncthreads();
        if (act && schg[slot] >= 0) {
            const int nidx = schg[slot], oidx = sold[slot];
            if (st < ND) {
                // rewrite quantized row
                out[Q_OFF + (size_t)b * ND * NT + (size_t)st * NT + t] = emb[nidx * ND + st];
            }
            if (st == 0) {
                // loss delta + histogram fix
                float delta = 0.f;
                const float* en_ = emb + nidx * ND;
                const float* eo_ = emb + oidx * ND;
                for (int d = 0; d < ND; d++) {
                    float xv = sx[slot][d];
                    float dn = en_[d] - xv;
                    float dl = eo_[d] - xv;
                    delta = __fmaf_rn(dn, dn, delta);
                    delta = __fmaf_rn(-dl, dl, delta);
                }
                atomicAdd(&g_loss, delta);
                atomicAdd(&g_counts[nidx], 1u);
                atomicAdd(&g_counts[oidx], (unsigned)-1);
            }
        }
        __syncthreads();
    }
}

// ================= K3: finalize =================
__global__ void vq_final(float* __restrict__ out) {
    __shared__ float red[32];
    int tid = threadIdx.x;
    if (tid < 32) red[tid] = 0.f;
    __syncthreads();
    unsigned c = g_counts[tid];
    float p = (float)c / (float)NTOK;
    float term = p * logf(p + 1e-10f);
    #pragma unroll
    for (int off = 16; off; off >>= 1)
        term += __shfl_down_sync(0xffffffffu, term, off);
    if ((tid & 31) == 0) red[tid >> 5] = term;
    __syncthreads();
    if (tid < 32) {
        float v = red[tid];
        #pragma unroll
        for (int off = 16; off; off >>= 1)
            v += __shfl_down_sync(0xffffffffu, v, off);
        if (tid == 0) {
            out[PERP_OFF] = expf(-v);
            out[0] = 0.25f * g_loss / (float)((size_t)NTOK * ND);
        }
    }
}

extern "C" void kernel_launch(void* const* d_in, const int* in_sizes, int n_in,
                              void* d_out, int out_size) {
    const float* in  = (const float*)d_in[0];   // [32, 64, 4096]
    const float* emb = (const float*)d_in[1];   // [512, 64]
    float* out = (float*)d_out;

    // smem: sB + sA + sEn + sXnP + sXn + bF + sF + iF + sIdx + sCount
    size_t smem = (size_t)(NK * ESTR + TM * ESTR + NK + 512 + TM * 5 + NK) * sizeof(float);
    cudaFuncSetAttribute(vq_gemm, cudaFuncAttributeMaxDynamicSharedMemorySize, (int)smem);

    vq_init<<<1, 512>>>();
    vq_gemm<<<NCTA, 512, smem>>>(in, emb, out);
    vq_cleanup<<<NCTA, 512>>>(in, emb, out);
    vq_final<<<1, 512>>>(out);
}